// round 16
// baseline (speedup 1.0000x reference)
#include <cuda_runtime.h>
#include <stdint.h>

#define NALGOS 64
#define NTASKS 1024
#define LXN    512
#define FULLMASK 0xffffffffu

// Scratch (no allocations allowed).
// g_G[s*512 + t] = TM[lx[s]][lx[t]]
__device__ float g_G[LXN * LXN];
__device__ float g_u[NALGOS * LXN];

// 2*sigmoid(z) - 1 == tanh(z/2): single MUFU.TANH, abs err ~2^-11.
__device__ __forceinline__ float tanh_fast(float x) {
    float y;
    asm("tanh.approx.f32 %0, %1;" : "=f"(y) : "f"(x));
    return y;
}
__device__ __forceinline__ void stcs_f32(float* p, float v) {
    asm volatile("st.global.cs.f32 [%0], %1;" :: "l"(p), "f"(v) : "memory");
}

// ---------------------------------------------------------------------------
// Kernel 0: G[s][t] = TM[lx[s]][lx[t]]
// ---------------------------------------------------------------------------
__global__ void build_G(const int* __restrict__ lx, const float* __restrict__ TM) {
    int s = blockIdx.x;
    int t = threadIdx.x;
    int row = __ldg(lx + s);
    int col = __ldg(lx + t);
    g_G[s * LXN + t] = __ldg(TM + row * NTASKS + col);
}

// ---------------------------------------------------------------------------
// Phase 1 (R9-exact, measured 22.5us): blocked-scan chain, 8-warp block/algo.
// ---------------------------------------------------------------------------
__global__ void __launch_bounds__(256, 1) phase1(
    const int* __restrict__ lx, const float* __restrict__ diff,
    const float* __restrict__ eff_, const float* __restrict__ mem_,
    const float* __restrict__ boost_) {

    __shared__ float u_sh[LXN];
    __shared__ float c2_sh[LXN];
    __shared__ float Bnext[2][32];

    int a   = blockIdx.x;
    int tid = threadIdx.x;
    int w = tid >> 5, l = tid & 31;

    float mem = __ldg(mem_ + a), eff = __ldg(eff_ + a), boost = __ldg(boost_ + a);
    float m2 = mem * mem, m4 = m2 * m2, m8 = m4 * m4, m16 = m8 * m8;
    float M32 = m16 * m16;

    for (int t = tid; t < LXN; t += 256)
        c2_sh[t] = 0.5f / __ldg(diff + __ldg(lx + t));
    __syncthreads();

    if (w == 0) {
        float racc = 0.0f, racc2 = 0.0f;
        float c2l = c2_sh[l];
        float my_u = 0.0f;

#pragma unroll 1
        for (int c = 0; c < 16; ++c) {
            int t0 = c * 32;
            const float* gArow = g_G + t0 + l;
            const float* gBrow = g_G + t0 + 32 + l;
            bool hasB = (c < 15);

            float gAe[8], gAb[8], gBe[8], gBb[8];
#pragma unroll
            for (int q = 0; q < 8; ++q) {
                float ga = __ldg(gArow + (t0 + q) * LXN);
                float gb = hasB ? __ldg(gBrow + (t0 + q) * LXN) : 0.0f;
                gAe[q] = ga * eff;  gAb[q] = ga * boost;
                gBe[q] = gb * eff;  gBb[q] = gb * boost;
            }
#pragma unroll
            for (int k = 0; k < 32; ++k) {
                int q = k & 7;
                float th = tanh_fast(racc * c2l);
                float thb = __shfl_sync(FULLMASK, th, k);
                my_u = (l == k) ? fmaf(th, boost, eff) : my_u;
                racc  = fmaf(thb, gAb[q], fmaf(racc,  mem, gAe[q]));
                racc2 = fmaf(thb, gBb[q], fmaf(racc2, mem, gBe[q]));
                if (k + 8 < 32) {
                    float ga = __ldg(gArow + (t0 + k + 8) * LXN);
                    float gb = hasB ? __ldg(gBrow + (t0 + k + 8) * LXN) : 0.0f;
                    gAe[q] = ga * eff;  gAb[q] = ga * boost;
                    gBe[q] = gb * eff;  gBb[q] = gb * boost;
                }
            }
            u_sh[t0 + l] = my_u;
            __syncthreads();
            if (c < 15) {
                racc  = fmaf(Bnext[(c + 1) & 1][l], M32, racc2);
                racc2 = 0.0f;
                c2l   = c2_sh[t0 + 32 + l];
            }
        }
    } else {
        int base0 = (w - 1) * 32 + l;
        bool has3 = (base0 + 448 < LXN);
        float R0 = 0.0f, R1 = 0.0f, R2v = 0.0f;

#pragma unroll 1
        for (int c = 0; c < 16; ++c) {
            if (c >= 1) {
                int s0 = (c - 1) * 32;
                const float* g0 = g_G + base0;
#pragma unroll 8
                for (int k = 0; k < 32; ++k) {
                    float u = u_sh[s0 + k];
                    const float* gr = g0 + (s0 + k) * LXN;
                    R0 = fmaf(R0, mem, __ldg(gr) * u);
                    R1 = fmaf(R1, mem, __ldg(gr + 224) * u);
                    if (has3) R2v = fmaf(R2v, mem, __ldg(gr + 448) * u);
                }
            }
            int b = c + 1;
            if (b <= 15 && (w - 1) == (b % 7)) {
                int i = b / 7;
                float Rv = (i == 0) ? R0 : (i == 1) ? R1 : R2v;
                Bnext[b & 1][l] = Rv;
            }
            __syncthreads();
        }
    }

    __syncthreads();
    for (int t = tid; t < LXN; t += 256)
        g_u[a * LXN + t] = u_sh[t];
}

// ---------------------------------------------------------------------------
// Phase 2 v6: DIAGONAL-STAGGERED scan -> perfectly aligned 128B stores.
// Thread (lane l) runs its column's scan offset by -l steps: at iteration c,
// lane l produces row elements t = 32c - l + k (k=0..31). Store op for
// (iteration c, tile-row r) covers flat [W + 512r + 32c, +32) — W ≡ 0 mod 32,
// so EVERY store is 128B-aligned, full-sector, RMW-free (st.cs safe).
// Coverage of the warp's 32x513 flat region is exact (slot 513r+t maps to
// unique c=(t+r)/32, lane=(t+r)%32); the t=0 zero and the final t=512 element
// are part of the same covering — no special-case stores at all.
// TM values staged per-chunk in double-buffered smem (lanes need different
// steps now); bank-conflict-free since 256 = 0 mod 32 banks.
// ---------------------------------------------------------------------------
__global__ void __launch_bounds__(256) phase2(
    const int* __restrict__ lx, const float* __restrict__ TM,
    const float* __restrict__ diff, const float* __restrict__ mem_,
    float* __restrict__ out) {

    __shared__ float u_sh[LXN];
    __shared__ int   off_sh[LXN];
    __shared__ float v_sh[2][32][256];         // [buf][step-in-chunk][j]
    __shared__ float tbuf_all[8][32][33];

    int a   = blockIdx.y;
    int jb  = blockIdx.x;
    int tid = threadIdx.x;
    int w = tid >> 5, l = tid & 31;
    int j = jb * 256 + tid;

    for (int i = tid; i < LXN; i += 256) {
        u_sh[i]   = g_u[a * LXN + i];
        off_sh[i] = __ldg(lx + i) << 10;
    }
    __syncthreads();

    // preload chunk 0 into buf 0
    {
        const float* TMj = TM + jb * 256 + tid;
#pragma unroll 8
        for (int k = 0; k < 32; ++k)
            v_sh[0][k][tid] = __ldg(TMj + off_sh[k]);
    }

    float mem = __ldg(mem_ + a);
    float c2  = 0.5f / __ldg(diff + j);
    float racc = 0.0f;
    float (*tbuf)[33] = tbuf_all[w];

    unsigned Wbase = (unsigned)(a * NTASKS + jb * 256 + w * 32) * 513u;

#pragma unroll 1
    for (int c = 0; c <= 16; ++c) {
        if (c >= 1) {
            __syncthreads();                   // buf (c&1)'s old chunk fully consumed
            if (c <= 15) {
                const float* TMj = TM + jb * 256 + tid;
                const int* offc = off_sh + c * 32;
#pragma unroll 8
                for (int k = 0; k < 32; ++k)
                    v_sh[c & 1][k][tid] = __ldg(TMj + offc[k]);
            }
            __syncthreads();                   // chunk c visible
        } else {
            __syncthreads();                   // chunk 0 visible to all warps
        }

        // compute: lane l produces elements t = 32c - l + k
        int tb = 32 * c - l;
#pragma unroll
        for (int k = 0; k < 32; ++k) {
            int t = tb + k;
            int step = t - 1;
            step = (step < 0) ? 0 : (step > 511 ? 511 : step);
            float vv = v_sh[(step >> 5) & 1][step & 31][tid];
            float cand = fmaf(racc, mem, vv * u_sh[step]);
            racc = (t >= 1 && t <= 512) ? cand : racc;
            float elem = tanh_fast(racc * c2);
            elem = (t <= 0) ? 0.0f : elem;
            tbuf[l][k] = elem;
        }
        __syncwarp();

        // aligned stores: op (c, row) -> flat [W + 512*row + 32*c, +32)
        unsigned ob = Wbase + (unsigned)(32 * c) + (unsigned)l;
        if (c >= 1 && c <= 15) {
#pragma unroll 8
            for (int row = 0; row < 32; ++row)
                stcs_f32(out + ob + 512u * (unsigned)row, tbuf[row][l]);
        } else {
#pragma unroll 8
            for (int row = 0; row < 32; ++row) {
                int t = 32 * c - row + l;
                if (t >= 0 && t <= 512)
                    stcs_f32(out + ob + 512u * (unsigned)row, tbuf[row][l]);
            }
        }
        __syncwarp();
    }
}

// ---------------------------------------------------------------------------
extern "C" void kernel_launch(void* const* d_in, const int* in_sizes, int n_in,
                              void* d_out, int out_size) {
    const int*   lx    = (const int*)  d_in[0];
    const float* TM    = (const float*)d_in[1];
    const float* diff  = (const float*)d_in[2];
    const float* eff   = (const float*)d_in[3];
    const float* mem   = (const float*)d_in[4];
    const float* boost = (const float*)d_in[5];
    float* out = (float*)d_out;

    build_G<<<LXN, LXN>>>(lx, TM);
    phase1<<<NALGOS, 256>>>(lx, diff, eff, mem, boost);
    phase2<<<dim3(4, NALGOS), 256>>>(lx, TM, diff, mem, out);
}

// round 17
// speedup vs baseline: 1.9338x; 1.9338x over previous
#include <cuda_runtime.h>
#include <stdint.h>

#define NALGOS 64
#define NTASKS 1024
#define LXN    512
#define FULLMASK 0xffffffffu

// Scratch (no allocations allowed).
// g_G[s*512 + t] = TM[lx[s]][lx[t]]
__device__ float g_G[LXN * LXN];
__device__ float g_u[NALGOS * LXN];

// 2*sigmoid(z) - 1 == tanh(z/2): single MUFU.TANH, abs err ~2^-11.
__device__ __forceinline__ float tanh_fast(float x) {
    float y;
    asm("tanh.approx.f32 %0, %1;" : "=f"(y) : "f"(x));
    return y;
}
__device__ __forceinline__ void stcs_f32(float* p, float v) {
    asm volatile("st.global.cs.f32 [%0], %1;" :: "l"(p), "f"(v) : "memory");
}

// ---------------------------------------------------------------------------
// Kernel 0: G[s][t] = TM[lx[s]][lx[t]]
// ---------------------------------------------------------------------------
__global__ void build_G(const int* __restrict__ lx, const float* __restrict__ TM) {
    int s = blockIdx.x;
    int t = threadIdx.x;
    int row = __ldg(lx + s);
    int col = __ldg(lx + t);
    g_G[s * LXN + t] = __ldg(TM + row * NTASKS + col);
}

// ---------------------------------------------------------------------------
// Phase 1 (R9-exact, measured 22.5us): blocked-scan chain, 8-warp block/algo.
// ---------------------------------------------------------------------------
__global__ void __launch_bounds__(256, 1) phase1(
    const int* __restrict__ lx, const float* __restrict__ diff,
    const float* __restrict__ eff_, const float* __restrict__ mem_,
    const float* __restrict__ boost_) {

    __shared__ float u_sh[LXN];
    __shared__ float c2_sh[LXN];
    __shared__ float Bnext[2][32];

    int a   = blockIdx.x;
    int tid = threadIdx.x;
    int w = tid >> 5, l = tid & 31;

    float mem = __ldg(mem_ + a), eff = __ldg(eff_ + a), boost = __ldg(boost_ + a);
    float m2 = mem * mem, m4 = m2 * m2, m8 = m4 * m4, m16 = m8 * m8;
    float M32 = m16 * m16;

    for (int t = tid; t < LXN; t += 256)
        c2_sh[t] = 0.5f / __ldg(diff + __ldg(lx + t));
    __syncthreads();

    if (w == 0) {
        float racc = 0.0f, racc2 = 0.0f;
        float c2l = c2_sh[l];
        float my_u = 0.0f;

#pragma unroll 1
        for (int c = 0; c < 16; ++c) {
            int t0 = c * 32;
            const float* gArow = g_G + t0 + l;
            const float* gBrow = g_G + t0 + 32 + l;
            bool hasB = (c < 15);

            float gAe[8], gAb[8], gBe[8], gBb[8];
#pragma unroll
            for (int q = 0; q < 8; ++q) {
                float ga = __ldg(gArow + (t0 + q) * LXN);
                float gb = hasB ? __ldg(gBrow + (t0 + q) * LXN) : 0.0f;
                gAe[q] = ga * eff;  gAb[q] = ga * boost;
                gBe[q] = gb * eff;  gBb[q] = gb * boost;
            }
#pragma unroll
            for (int k = 0; k < 32; ++k) {
                int q = k & 7;
                float th = tanh_fast(racc * c2l);
                float thb = __shfl_sync(FULLMASK, th, k);
                my_u = (l == k) ? fmaf(th, boost, eff) : my_u;
                racc  = fmaf(thb, gAb[q], fmaf(racc,  mem, gAe[q]));
                racc2 = fmaf(thb, gBb[q], fmaf(racc2, mem, gBe[q]));
                if (k + 8 < 32) {
                    float ga = __ldg(gArow + (t0 + k + 8) * LXN);
                    float gb = hasB ? __ldg(gBrow + (t0 + k + 8) * LXN) : 0.0f;
                    gAe[q] = ga * eff;  gAb[q] = ga * boost;
                    gBe[q] = gb * eff;  gBb[q] = gb * boost;
                }
            }
            u_sh[t0 + l] = my_u;
            __syncthreads();
            if (c < 15) {
                racc  = fmaf(Bnext[(c + 1) & 1][l], M32, racc2);
                racc2 = 0.0f;
                c2l   = c2_sh[t0 + 32 + l];
            }
        }
    } else {
        int base0 = (w - 1) * 32 + l;
        bool has3 = (base0 + 448 < LXN);
        float R0 = 0.0f, R1 = 0.0f, R2v = 0.0f;

#pragma unroll 1
        for (int c = 0; c < 16; ++c) {
            if (c >= 1) {
                int s0 = (c - 1) * 32;
                const float* g0 = g_G + base0;
#pragma unroll 8
                for (int k = 0; k < 32; ++k) {
                    float u = u_sh[s0 + k];
                    const float* gr = g0 + (s0 + k) * LXN;
                    R0 = fmaf(R0, mem, __ldg(gr) * u);
                    R1 = fmaf(R1, mem, __ldg(gr + 224) * u);
                    if (has3) R2v = fmaf(R2v, mem, __ldg(gr + 448) * u);
                }
            }
            int b = c + 1;
            if (b <= 15 && (w - 1) == (b % 7)) {
                int i = b / 7;
                float Rv = (i == 0) ? R0 : (i == 1) ? R1 : R2v;
                Bnext[b & 1][l] = Rv;
            }
            __syncthreads();
        }
    }

    __syncthreads();
    for (int t = tid; t < LXN; t += 256)
        g_u[a * LXN + t] = u_sh[t];
}

// ---------------------------------------------------------------------------
// Phase 2 v7: R9 scan + DOUBLE-BUFFERED transpose tile + DIAGONAL ALIGNED
// stores. Store op (c,row) covers flat [W + 512*row + 32c, +32) — always
// 128B-aligned, full-sector, RMW-free with st.cs. Element for lane l comes
// from tile c (l>row) or tile c-1 (l<=row) at k=(l-row-1)&31; one LDS,
// bank = (l-1) mod 32 per lane -> conflict-free. Exact covering of each
// 513-float row incl. the t=0 zero (op 0, lane==row) and t=512 (op 16).
// 128-thread blocks (4 warps) keep the 2-buffer tile in 38KB static smem.
// ---------------------------------------------------------------------------
__global__ void __launch_bounds__(128) phase2(
    const int* __restrict__ lx, const float* __restrict__ TM,
    const float* __restrict__ diff, const float* __restrict__ mem_,
    float* __restrict__ out) {

    __shared__ float u_sh[LXN];
    __shared__ int   off_sh[LXN];
    __shared__ float tb_all[4][2][32 * 33];    // [warp][buffer][row*33+k]

    int a   = blockIdx.y;
    int jb  = blockIdx.x;                      // 8 tiles of 128 columns
    int tid = threadIdx.x;
    int w = tid >> 5, l = tid & 31;
    int j = jb * 128 + tid;

    for (int i = tid; i < LXN; i += 128) {
        u_sh[i]   = g_u[a * LXN + i];
        off_sh[i] = __ldg(lx + i) << 10;
    }
    __syncthreads();

    float mem = __ldg(mem_ + a);
    float c2  = 0.5f / __ldg(diff + j);
    float r   = 0.0f;
    const float* TMj = TM + j;

    unsigned W = (unsigned)(a * NTASKS + jb * 128 + w * 32) * 513u;

#pragma unroll 1
    for (int c = 0; c < 16; ++c) {
        // 1) register prefetch of the chunk's TM values (R9-proven)
        float v[32];
#pragma unroll
        for (int k = 0; k < 32; ++k)
            v[k] = __ldg(TMj + off_sh[c * 32 + k]);
        // 2) scan + tanh into this chunk's tile buffer
        float* tc = tb_all[w][c & 1];
#pragma unroll
        for (int k = 0; k < 32; ++k) {
            r = fmaf(r, mem, v[k] * u_sh[c * 32 + k]);
            tc[l * 33 + k] = tanh_fast(r * c2);
        }
        __syncwarp();
        // 3) diagonal aligned stores for op c
        const float* tp = tb_all[w][(c + 1) & 1];   // chunk c-1's tile
        unsigned ob = W + (unsigned)(32 * c) + (unsigned)l;
        if (c == 0) {
            // lanes l>row: t=l-row from tile0; lane l==row: t=0 -> 0.0f;
            // lanes l<row: outside this row (covered by op16 of row-1) -> masked
#pragma unroll
            for (int row = 0; row < 32; ++row) {
                if (l > row)
                    stcs_f32(out + ob + 512u * (unsigned)row,
                             tc[row * 33 + (l - row - 1)]);
                else if (l == row)
                    stcs_f32(out + ob + 512u * (unsigned)row, 0.0f);
            }
        } else {
#pragma unroll
            for (int row = 0; row < 32; ++row) {
                int kk = (l - row - 1) & 31;               // uniform k formula
                const float* src = (l > row) ? tc : tp;
                stcs_f32(out + ob + 512u * (unsigned)row, src[row * 33 + kk]);
            }
        }
        __syncwarp();
    }
    // 4) final op c=16: tail elements t in (512-row, 512] from tile 15 (buf 1)
    {
        const float* tp = tb_all[w][15 & 1];
        unsigned ob = W + 512u + (unsigned)l;
#pragma unroll
        for (int row = 0; row < 32; ++row) {
            if (l <= row) {
                int kk = (l - row - 1) & 31;               // = 31-row+l
                stcs_f32(out + ob + 512u * (unsigned)row, tp[row * 33 + kk]);
            }
        }
    }
}

// ---------------------------------------------------------------------------
extern "C" void kernel_launch(void* const* d_in, const int* in_sizes, int n_in,
                              void* d_out, int out_size) {
    const int*   lx    = (const int*)  d_in[0];
    const float* TM    = (const float*)d_in[1];
    const float* diff  = (const float*)d_in[2];
    const float* eff   = (const float*)d_in[3];
    const float* mem   = (const float*)d_in[4];
    const float* boost = (const float*)d_in[5];
    float* out = (float*)d_out;

    build_G<<<LXN, LXN>>>(lx, TM);
    phase1<<<NALGOS, 256>>>(lx, diff, eff, mem, boost);
    phase2<<<dim3(8, NALGOS), 128>>>(lx, TM, diff, mem, out);
}